// round 14
// baseline (speedup 1.0000x reference)
#include <cuda_runtime.h>
#include <cuda.h>
#include <cuda_fp16.h>
#include <cstdint>

#define N_REL   65536
#define D_FEAT  3872
#define D_OUT   512
#define N_CLS   36
#define NTOT    1536            // 3 heads * 512
#define KCHUNK  64              // halfs per K tile (128 bytes)
#define NK      61              // ceil(3872/64); last chunk TMA zero-fills 32 halfs
#define TM      256             // per-CTA M (2 x 128-row MMAs)
#define TN      256
#define STAGES  3
#define STAGE_BYTES 65536       // A 32KB + B 32KB
#define NCHUNK  8               // X-convert / GEMM pipeline chunks
#define MT_PER_CHUNK (N_REL / TM / NCHUNK)   // 32 M-tiles per chunk
#define ROWS_PER_CHUNK (N_REL / NCHUNK)      // 8192 rows (= 1 << 13)

#if defined(__CUDA_ARCH_FEAT_SM103_ALL) || defined(__CUDA_ARCH_FEAT_SM100_ALL) || defined(__CUDA_ARCH_FEAT_SM101_ALL)
#define HAS_TCGEN05 1
#else
#define HAS_TCGEN05 0
#endif

// ---------------- device scratch ----------------
__device__ int g_cnt[N_CLS];
__device__ int g_off[N_CLS + 1];
__device__ int g_poff[N_CLS];
__device__ int g_sorted[N_REL];
__device__ int g_lo[N_REL];
__device__ int g_hi[N_REL];
__device__ __half g_wth[(size_t)NTOT * D_FEAT];        // 12 MB, K-major fp16 weights
__device__ __half g_xh[(size_t)N_REL * D_FEAT];        // 507 MB, fp16 X
__device__ __half g_yh[(size_t)N_REL * NTOT];          // 201 MB, Y = X @ W (fp16, no bias)

// ---------------- PTX helpers ----------------
__device__ __forceinline__ uint32_t smem_to_u32(const void* p) {
    uint32_t a;
    asm("{ .reg .u64 t; cvta.to.shared.u64 t, %1; cvt.u32.u64 %0, t; }" : "=r"(a) : "l"(p));
    return a;
}
#define MBARRIER_INIT(mbar, cnt) \
    asm volatile("mbarrier.init.shared.b64 [%0], %1;" :: "r"((uint32_t)(mbar)), "r"((uint32_t)(cnt)) : "memory")
#define MBARRIER_EXPECT_TX(mbar, bytes) \
    asm volatile("mbarrier.arrive.expect_tx.shared.b64 _, [%0], %1;" \
                 :: "r"((uint32_t)(mbar)), "r"((uint32_t)(bytes)) : "memory")
#define MBARRIER_WAIT_PARITY(mbar, par) do {                                        \
    uint32_t _m = (uint32_t)(mbar); uint32_t _p = (uint32_t)(par); uint32_t _d;     \
    asm volatile("{\n\t.reg .pred p;\n\t"                                           \
        "mbarrier.try_wait.parity.acquire.cta.shared::cta.b64 p, [%1], %2;\n\t"     \
        "selp.b32 %0, 1, 0, p;\n\t}" : "=r"(_d) : "r"(_m), "r"(_p) : "memory");     \
    if (!_d) {                                                                      \
        asm volatile("{\n\t.reg .pred P1;\n\t"                                      \
        "WL_%=:\n\tmbarrier.try_wait.parity.acquire.cta.shared::cta.b64 P1, [%0], %1, 0x989680;\n\t" \
        "@P1 bra.uni WD_%=;\n\tbra.uni WL_%=;\n\tWD_%=:\n\t}"                       \
        :: "r"(_m), "r"(_p) : "memory");                                            \
    } } while (0)

#if HAS_TCGEN05
__device__ __forceinline__ uint32_t elect_one_pred() {
    uint32_t pred;
    asm volatile("{\n\t.reg .pred p;\n\telect.sync _|p, 0xFFFFFFFF;\n\tselp.b32 %0, 1, 0, p;\n\t}"
                 : "=r"(pred));
    return pred;
}
#define TMA_LOAD_2D(smem, tmap, cx, cy, mbar) \
    asm volatile("cp.async.bulk.tensor.2d.shared::cta.global.tile.mbarrier::complete_tx::bytes " \
                 "[%0], [%1, {%2, %3}], [%4];" \
                 :: "r"((uint32_t)(smem)), "l"(tmap), "r"((int)(cx)), "r"((int)(cy)), \
                    "r"((uint32_t)(mbar)) : "memory")
#define TCGEN05_ALLOC(sr, nc) \
    asm volatile("tcgen05.alloc.cta_group::1.sync.aligned.shared::cta.b32 [%0], %1;" \
                 :: "r"((uint32_t)(sr)), "r"((uint32_t)(nc)) : "memory")
#define TCGEN05_DEALLOC(t, nc) \
    asm volatile("tcgen05.dealloc.cta_group::1.sync.aligned.b32 %0, %1;" :: "r"(t), "r"((uint32_t)(nc)))
#define TCGEN05_RELINQ() \
    asm volatile("tcgen05.relinquish_alloc_permit.cta_group::1.sync.aligned;")
#define TCGEN05_COMMIT(mbar) \
    asm volatile("tcgen05.commit.cta_group::1.mbarrier::arrive::one.shared::cluster.b64 [%0];" \
                 :: "r"((uint32_t)(mbar)) : "memory")
#define TCGEN05_FENCE_AFTER()  asm volatile("tcgen05.fence::after_thread_sync;" ::: "memory")
#define TCGEN05_FENCE_BEFORE() asm volatile("tcgen05.fence::before_thread_sync;" ::: "memory")
#define TCGEN05_WAIT_LD()      asm volatile("tcgen05.wait::ld.sync.aligned;" ::: "memory")
#define TCGEN05_LD_X32(r, ta) \
    asm volatile("tcgen05.ld.sync.aligned.32x32b.x32.b32 " \
        "{%0,%1,%2,%3,%4,%5,%6,%7,%8,%9,%10,%11,%12,%13,%14,%15," \
        "%16,%17,%18,%19,%20,%21,%22,%23,%24,%25,%26,%27,%28,%29,%30,%31}, [%32];" \
        : "=r"((r)[0]),"=r"((r)[1]),"=r"((r)[2]),"=r"((r)[3]),"=r"((r)[4]),"=r"((r)[5]),"=r"((r)[6]),"=r"((r)[7]), \
          "=r"((r)[8]),"=r"((r)[9]),"=r"((r)[10]),"=r"((r)[11]),"=r"((r)[12]),"=r"((r)[13]),"=r"((r)[14]),"=r"((r)[15]), \
          "=r"((r)[16]),"=r"((r)[17]),"=r"((r)[18]),"=r"((r)[19]),"=r"((r)[20]),"=r"((r)[21]),"=r"((r)[22]),"=r"((r)[23]), \
          "=r"((r)[24]),"=r"((r)[25]),"=r"((r)[26]),"=r"((r)[27]),"=r"((r)[28]),"=r"((r)[29]),"=r"((r)[30]),"=r"((r)[31]) \
        : "r"(ta))

static constexpr uint64_t SMEM_DESC_BASE_SW128 =
    (uint64_t(2) << 61) | (uint64_t(1) << 46) | (uint64_t(64) << 32) | (uint64_t(1) << 16);
__device__ __forceinline__ uint64_t make_desc(uint32_t addr) {
    return SMEM_DESC_BASE_SW128 | ((uint64_t)(addr >> 4) & 0x3FFF);
}
// kind::f16 SS MMA (fp16 in, fp32 accum)
__device__ __forceinline__ void mma_f16_ss(uint32_t d, uint64_t a, uint64_t b,
                                           uint32_t idesc, uint32_t en) {
    asm volatile("{\n\t.reg .pred p;\n\tsetp.ne.u32 p, %5, 0;\n\t"
        "tcgen05.mma.cta_group::1.kind::f16 [%0], %1, %2, %3, {%4, %4, %4, %4}, p;\n\t}"
        :: "r"(d), "l"(a), "l"(b), "r"(idesc), "r"(0u), "r"(en) : "memory");
}
// dtype=f32(1)<<4 | atype=F16(0)<<7 | btype=F16(0)<<10 | N=256 | M=128
static constexpr uint32_t IDESC = (1u << 4) | ((TN / 8) << 17) | ((128 / 16) << 24);
#endif  // HAS_TCGEN05

// ---------------- index construction ----------------
__global__ void k_zero() { if (threadIdx.x < N_CLS) g_cnt[threadIdx.x] = 0; }

__global__ void k_hist(const int* __restrict__ lab) {     // <<<64, 1024>>>
    __shared__ int h[N_CLS];
    if (threadIdx.x < N_CLS) h[threadIdx.x] = 0;
    __syncthreads();
    int i = blockIdx.x * blockDim.x + threadIdx.x;
    atomicAdd(&h[lab[i]], 1);
    __syncthreads();
    if (threadIdx.x < N_CLS) atomicAdd(&g_cnt[threadIdx.x], h[threadIdx.x]);
}
__global__ void k_scan() {
    if (threadIdx.x == 0) {
        int run = 0, prun = 0;
        g_off[0] = 0;
        for (int c = 0; c < N_CLS; c++) {
            g_poff[c] = prun;
            int cnt = g_cnt[c];
            run += cnt; g_off[c + 1] = run;
            prun += (cnt > 0) ? (cnt - 1) : 0;
        }
    }
}
__global__ void k_rank(const int* __restrict__ lab) {     // <<<36, 1024>>>
    const int c = blockIdx.x, tid = threadIdx.x;
    __shared__ int wsum[32];
    const int base_off = g_off[c];
    int sbase = 0;
    for (int start = 0; start < N_REL; start += 1024) {
        int i = start + tid;
        int flag = (lab[i] == c) ? 1 : 0;
        unsigned mask = __ballot_sync(0xffffffffu, flag);
        if ((tid & 31) == 0) wsum[tid >> 5] = __popc(mask);
        __syncthreads();
        int wbase = 0, total = 0, wi = tid >> 5;
        #pragma unroll
        for (int j = 0; j < 32; j++) { int v = wsum[j]; total += v; if (j < wi) wbase += v; }
        if (flag) {
            int excl = __popc(mask & ((1u << (tid & 31)) - 1u));
            g_sorted[base_off + sbase + wbase + excl] = i;
        }
        sbase += total;
        __syncthreads();
    }
}
__global__ void k_pairs(const int* __restrict__ lab) {
    int p = blockIdx.x * blockDim.x + threadIdx.x;
    if (p >= N_REL) return;
    int io = g_sorted[p];
    int c = lab[io];
    if (p + 1 < g_off[c + 1]) {
        int m = p - g_off[c] + g_poff[c];
        g_lo[m] = io; g_hi[m] = g_sorted[p + 1];
    }
}

// ---------------- convert an X row-chunk to fp16 ----------------
__global__ void k_xh(const float* __restrict__ X, int row0) {   // <<<1024, 256>>>
    const size_t base = (size_t)row0 * D_FEAT / 4;
    const size_t total = (size_t)ROWS_PER_CHUNK * D_FEAT / 4;
    const float4* __restrict__ src = (const float4*)X + base;
    __half2* __restrict__ dst = (__half2*)g_xh + base * 2;
    for (size_t q = (size_t)blockIdx.x * blockDim.x + threadIdx.x;
         q < total; q += (size_t)gridDim.x * blockDim.x) {
        float4 v = src[q];
        dst[q * 2]     = __floats2half2_rn(v.x, v.y);
        dst[q * 2 + 1] = __floats2half2_rn(v.z, v.w);
    }
}

// ---------------- transpose + convert weights to K-major fp16 ----------------
__global__ void k_wt(const float* __restrict__ Wa, const float* __restrict__ Ws,
                     const float* __restrict__ Wc) {
    __shared__ float tile[32][33];
    int kb = blockIdx.x * 32;
    int ng = blockIdx.y;
    int head = ng >> 4;
    const float* W = (head == 0) ? Wa : ((head == 1) ? Ws : Wc);
    int nb = (ng & 15) * 32;
    int tx = threadIdx.x, ty = threadIdx.y;  // (32, 8)
    #pragma unroll
    for (int r = 0; r < 4; r++) {
        int k = kb + ty + r * 8;
        tile[ty + r * 8][tx] = W[(size_t)k * D_OUT + nb + tx];
    }
    __syncthreads();
    #pragma unroll
    for (int r = 0; r < 4; r++) {
        int n = ng * 32 + ty + r * 8;
        g_wth[(size_t)n * D_FEAT + kb + tx] = __float2half_rn(tile[tx][ty + r * 8]);
    }
}

// ---------------- output diff epilogue: out = Y[hi] - Y[lo] + bias --------------
// Processes only rows whose max(hi,lo) GEMM-chunk is in [cmin, cmax).
__global__ void k_out(const float* __restrict__ ba, const float* __restrict__ bs,
                      const float* __restrict__ bc, float* __restrict__ out, int M,
                      int cmin, int cmax) {
    const int m = blockIdx.x;
    const int hi = g_hi[m], lo = g_lo[m];
    const int mx = (hi > lo ? hi : lo) >> 13;   // ROWS_PER_CHUNK = 8192
    if (mx < cmin || mx >= cmax) return;
    const int q = threadIdx.x;                 // 0..191, one uint4 (8 halfs) each
    const uint4* __restrict__ yh = (const uint4*)(g_yh + (size_t)hi * NTOT);
    const uint4* __restrict__ yl = (const uint4*)(g_yh + (size_t)lo * NTOT);
    uint4 A = yh[q], B = yl[q];
    const int col = q * 8;
    const int h = col >> 9;                    // head
    const int c = col & 511;                   // col within head
    const float* bias = (h == 0) ? ba : ((h == 1) ? bs : bc);
    float4 b0 = *(const float4*)(bias + c);
    float4 b1 = *(const float4*)(bias + c + 4);
    float2 a0 = __half22float2(*(__half2*)&A.x), l0 = __half22float2(*(__half2*)&B.x);
    float2 a1 = __half22float2(*(__half2*)&A.y), l1 = __half22float2(*(__half2*)&B.y);
    float2 a2 = __half22float2(*(__half2*)&A.z), l2 = __half22float2(*(__half2*)&B.z);
    float2 a3 = __half22float2(*(__half2*)&A.w), l3 = __half22float2(*(__half2*)&B.w);
    float* dst = out + ((size_t)h * M + m) * D_OUT + c;
    float4 o0, o1;
    o0.x = a0.x - l0.x + b0.x; o0.y = a0.y - l0.y + b0.y;
    o0.z = a1.x - l1.x + b0.z; o0.w = a1.y - l1.y + b0.w;
    o1.x = a2.x - l2.x + b1.x; o1.y = a2.y - l2.y + b1.y;
    o1.z = a3.x - l3.x + b1.z; o1.w = a3.y - l3.y + b1.w;
    *(float4*)(dst)     = o0;
    *(float4*)(dst + 4) = o1;
}

// ---------------- GEMM: Y = Xh @ Wth^T (fp16 in, fp32 accum, fp16 out) --------
// grid: x = 6 N-tiles (256 cols), y = 32 M-tiles per chunk; 256 threads.
__global__ __launch_bounds__(256, 1)
void k_gemm(const __grid_constant__ CUtensorMap tmA,
            const __grid_constant__ CUtensorMap tmB,
            const float* __restrict__ X,
            const float* __restrict__ Wa, const float* __restrict__ Ws,
            const float* __restrict__ Wc, __half* __restrict__ y, int yoff) {
    extern __shared__ char smem[];
#if HAS_TCGEN05
    // ======================= tcgen05 f16 + TMA path =======================
    const uint32_t sb = smem_to_u32(smem);
    // layout: [0..4) tmem ptr | [8..32) full[3] | [32..56) empty[3] | data @1024
    const uint32_t full0  = sb + 8;
    const uint32_t empty0 = sb + 32;
    const uint32_t data = (sb + 56 + 1023) & ~1023u;

    const int tid = threadIdx.x;
    const int wid = tid >> 5;
    const int lid = tid & 31;
    const int m0 = (blockIdx.y + yoff) * TM;
    const int n0 = blockIdx.x * TN;

    if (wid == 0) TCGEN05_ALLOC(sb, 512);
    if (tid == 0) {
        #pragma unroll
        for (int s = 0; s < STAGES; s++) {
            MBARRIER_INIT(full0 + s * 8, 1);     // expect_tx thread arrives
            MBARRIER_INIT(empty0 + s * 8, 1);    // tcgen05 commit arrives
        }
    }
    __syncthreads();
    uint32_t tmem;
    asm volatile("ld.shared.b32 %0, [%1];" : "=r"(tmem) : "r"(sb));

    const bool leader = (wid == 0) && elect_one_pred();

    if (leader) {
        // prologue: fill all stages
        #pragma unroll
        for (int i = 0; i < STAGES; i++) {
            uint32_t A_base = data + (uint32_t)i * STAGE_BYTES;
            MBARRIER_EXPECT_TX(full0 + i * 8, 2 * 32768u);
            TMA_LOAD_2D(A_base,          &tmA, i * KCHUNK, m0, full0 + i * 8);
            TMA_LOAD_2D(A_base + 32768u, &tmB, i * KCHUNK, n0, full0 + i * 8);
        }
        int s = 0, ph = 0;   // ph = (i / STAGES) & 1
        for (int i = 0; i < NK; i++) {
            const uint32_t A_base = data + (uint32_t)s * STAGE_BYTES;
            const uint32_t B_base = A_base + 32768u;
            MBARRIER_WAIT_PARITY(full0 + s * 8, ph);    // tiles arrived
            uint64_t ad0 = make_desc(A_base);
            uint64_t ad1 = make_desc(A_base + 16384u);   // rows 128..255
            uint64_t bd  = make_desc(B_base);
            #pragma unroll
            for (int ks = 0; ks < 4; ks++) {             // 4 x K=16 halfs = 64
                uint32_t en = (i > 0 || ks > 0) ? 1u : 0u;
                mma_f16_ss(tmem,       ad0 + ks * 2, bd + ks * 2, IDESC, en);
                mma_f16_ss(tmem + 256, ad1 + ks * 2, bd + ks * 2, IDESC, en);
            }
            TCGEN05_COMMIT(empty0 + s * 8);
            const int j = i + STAGES;
            if (j < NK) {
                // reuse stage s: wait for chunk i's MMAs to finish reading it
                MBARRIER_WAIT_PARITY(empty0 + s * 8, ph);
                MBARRIER_EXPECT_TX(full0 + s * 8, 2 * 32768u);
                TMA_LOAD_2D(A_base, &tmA, j * KCHUNK, m0, full0 + s * 8);
                TMA_LOAD_2D(B_base, &tmB, j * KCHUNK, n0, full0 + s * 8);
            }
            if (++s == STAGES) { s = 0; ph ^= 1; }
        }
        // leader is phase-paced: this waits for the FINAL commit (chunk NK-1)
        MBARRIER_WAIT_PARITY(empty0 + ((NK - 1) % STAGES) * 8, ((NK - 1) / STAGES) & 1);
    }
    __syncthreads();          // release all warps only after leader saw final commit
    TCGEN05_FENCE_AFTER();

    // epilogue: warps 0-3 -> rows m0..m0+127 (TMEM cols 0..255),
    //           warps 4-7 -> rows m0+128..m0+255 (TMEM cols 256..511)
    const uint32_t dbase = tmem + ((wid >= 4) ? 256u : 0u);
    const int m = m0 + ((wid >= 4) ? 128 : 0) + (wid & 3) * 32 + lid;
    __half* dst_row = y + (size_t)m * NTOT + n0;

    #pragma unroll
    for (int cc = 0; cc < 256; cc += 32) {
        uint32_t r[32];
        TCGEN05_LD_X32(r, dbase + cc);
        TCGEN05_WAIT_LD();
        #pragma unroll
        for (int q = 0; q < 4; q++) {
            __half2 h0 = __floats2half2_rn(__uint_as_float(r[q*8+0]), __uint_as_float(r[q*8+1]));
            __half2 h1 = __floats2half2_rn(__uint_as_float(r[q*8+2]), __uint_as_float(r[q*8+3]));
            __half2 h2 = __floats2half2_rn(__uint_as_float(r[q*8+4]), __uint_as_float(r[q*8+5]));
            __half2 h3 = __floats2half2_rn(__uint_as_float(r[q*8+6]), __uint_as_float(r[q*8+7]));
            uint4 o;
            o.x = *(uint32_t*)&h0; o.y = *(uint32_t*)&h1;
            o.z = *(uint32_t*)&h2; o.w = *(uint32_t*)&h3;
            *(uint4*)(dst_row + cc + q * 8) = o;
        }
    }
    TCGEN05_FENCE_BEFORE();
    __syncthreads();
    if (wid == 0) {
        TCGEN05_RELINQ();
        TCGEN05_DEALLOC(tmem, 512);
    }
#else
    // ======================= SIMT fallback (compute_103 pass) =======================
    float (*As)[128] = (float(*)[128])smem;                       // [16][128]
    float (*Bs)[128] = (float(*)[128])(smem + 16 * 128 * 4);      // [16][128]
    const int tid = threadIdx.x;
    const int tx = tid & 15;
    const int ty = tid >> 4;

    for (int mh = 0; mh < 2; mh++) {
        const int m0 = (blockIdx.y + yoff) * TM + mh * 128;
        for (int h = 0; h < 2; h++) {
            const int n0 = blockIdx.x * TN + h * 128;
            const int head = n0 / D_OUT;
            const int ncl = n0 % D_OUT;
            const float* __restrict__ W = (head == 0) ? Wa : ((head == 1) ? Ws : Wc);

            float acc[8][8];
            #pragma unroll
            for (int i = 0; i < 8; i++)
                #pragma unroll
                for (int j = 0; j < 8; j++) acc[i][j] = 0.0f;

            for (int k0 = 0; k0 < D_FEAT; k0 += 16) {
                #pragma unroll
                for (int jj = 0; jj < 2; jj++) {
                    int idx = tid * 2 + jj;
                    int row = idx >> 2, kq = idx & 3;
                    float4 v = *(const float4*)(X + (size_t)(m0 + row) * D_FEAT + k0 + kq * 4);
                    As[kq * 4 + 0][row] = v.x; As[kq * 4 + 1][row] = v.y;
                    As[kq * 4 + 2][row] = v.z; As[kq * 4 + 3][row] = v.w;
                }
                #pragma unroll
                for (int jj = 0; jj < 2; jj++) {
                    int l = tid * 2 + jj;
                    int k = l >> 5, nq = l & 31;
                    *(float4*)&Bs[k][nq * 4] =
                        *(const float4*)(W + (size_t)(k0 + k) * D_OUT + ncl + nq * 4);
                }
                __syncthreads();
                #pragma unroll
                for (int k = 0; k < 16; k++) {
                    float4 a0 = *(const float4*)&As[k][ty * 8];
                    float4 a1 = *(const float4*)&As[k][ty * 8 + 4];
                    float4 b0 = *(const float4*)&Bs[k][tx * 8];
                    float4 b1 = *(const float4*)&Bs[k][tx * 8 + 4];
                    float av[8] = {a0.x, a0.y, a0.z, a0.w, a1.x, a1.y, a1.z, a1.w};
                    float bv[8] = {b0.x, b0.y, b0.z, b0.w, b1.x, b1.y, b1.z, b1.w};
                    #pragma unroll
                    for (int i = 0; i < 8; i++)
                        #pragma unroll
                        for (int j = 0; j < 8; j++)
                            acc[i][j] = fmaf(av[i], bv[j], acc[i][j]);
                }
                __syncthreads();
            }

            #pragma unroll
            for (int i = 0; i < 8; i++) {
                int gm = (blockIdx.y + yoff) * TM + mh * 128 + ty * 8 + i;
                __half* dst = y + (size_t)gm * NTOT + n0 + tx * 8;
                #pragma unroll
                for (int j = 0; j < 8; j++) dst[j] = __float2half_rn(acc[i][j]);
            }
            __syncthreads();
        }
    }
#endif
}

// ---------------- launch ----------------
typedef CUresult (*encode_fn_t)(CUtensorMap*, CUtensorMapDataType, cuuint32_t, void*,
                                const cuuint64_t*, const cuuint64_t*, const cuuint32_t*,
                                const cuuint32_t*, CUtensorMapInterleave, CUtensorMapSwizzle,
                                CUtensorMapL2promotion, CUtensorMapFloatOOBfill);

static void make_tmap_f16(encode_fn_t enc, CUtensorMap* tm, void* base,
                          unsigned long long rows) {
    cuuint64_t dims[2]    = { (cuuint64_t)D_FEAT, (cuuint64_t)rows };
    cuuint64_t strides[1] = { (cuuint64_t)D_FEAT * sizeof(__half) };
    cuuint32_t box[2]     = { KCHUNK, 256u };    // 64 halfs = 128B (SW128 limit)
    cuuint32_t estr[2]    = { 1u, 1u };
    enc(tm, CU_TENSOR_MAP_DATA_TYPE_FLOAT16, 2, base, dims, strides, box, estr,
        CU_TENSOR_MAP_INTERLEAVE_NONE, CU_TENSOR_MAP_SWIZZLE_128B,
        CU_TENSOR_MAP_L2_PROMOTION_L2_128B, CU_TENSOR_MAP_FLOAT_OOB_FILL_NONE);
}

extern "C" void kernel_launch(void* const* d_in, const int* in_sizes, int n_in,
                              void* d_out, int out_size) {
    const float* X   = (const float*)d_in[0];
    const float* Wa  = (const float*)d_in[1];
    const float* ba  = (const float*)d_in[2];
    const float* Ws  = (const float*)d_in[3];
    const float* bs  = (const float*)d_in[4];
    const float* Wc  = (const float*)d_in[5];
    const float* bc  = (const float*)d_in[6];
    const int*   lab = (const int*)d_in[7];
    float* out = (float*)d_out;

    const int M = out_size / (3 * D_OUT);
    const int SMEM_TOTAL = STAGE_BYTES * STAGES + 1024 + 128;   // ~197.8 KB

    cudaFuncSetAttribute(k_gemm, cudaFuncAttributeMaxDynamicSharedMemorySize, SMEM_TOTAL);

    // one-time host objects (no device allocations) — proven 3-stream set.
    static encode_fn_t enc = nullptr;
    static cudaStream_t s2 = nullptr, s3 = nullptr;
    static cudaEvent_t eFork = nullptr, eJoin = nullptr, eWt = nullptr;
    static cudaEvent_t eX[NCHUNK] = {};
    static cudaEvent_t eG[NCHUNK] = {};
    static cudaEvent_t eP1 = nullptr, eP2 = nullptr;
    if (!enc) {
        cudaDriverEntryPointQueryResult qr;
        void* fp = nullptr;
#if CUDART_VERSION >= 12050
        cudaGetDriverEntryPointByVersion("cuTensorMapEncodeTiled", &fp, 12000,
                                         cudaEnableDefault, &qr);
#else
        cudaGetDriverEntryPoint("cuTensorMapEncodeTiled", &fp, cudaEnableDefault, &qr);
#endif
        enc = (encode_fn_t)fp;
    }
    if (!s2) {
        cudaStreamCreateWithFlags(&s2, cudaStreamNonBlocking);
        cudaStreamCreateWithFlags(&s3, cudaStreamNonBlocking);
        cudaEventCreateWithFlags(&eFork, cudaEventDisableTiming);
        cudaEventCreateWithFlags(&eJoin, cudaEventDisableTiming);
        cudaEventCreateWithFlags(&eWt, cudaEventDisableTiming);
        cudaEventCreateWithFlags(&eP1, cudaEventDisableTiming);
        cudaEventCreateWithFlags(&eP2, cudaEventDisableTiming);
        for (int c = 0; c < NCHUNK; c++) {
            cudaEventCreateWithFlags(&eX[c], cudaEventDisableTiming);
            cudaEventCreateWithFlags(&eG[c], cudaEventDisableTiming);
        }
    }

    void* wth_ptr = nullptr;
    cudaGetSymbolAddress(&wth_ptr, g_wth);
    void* xh_ptr = nullptr;
    cudaGetSymbolAddress(&xh_ptr, g_xh);
    void* y_ptr = nullptr;
    cudaGetSymbolAddress(&y_ptr, g_yh);

    CUtensorMap tmA, tmB;
    make_tmap_f16(enc, &tmA, xh_ptr, N_REL);
    make_tmap_f16(enc, &tmB, wth_ptr, NTOT);

    // fork (R10 schedule): s2 = weights + index chain + overlapped k_out parts;
    //                      s3 = X conversion chunks; main = all GEMM chunks + final k_out
    cudaEventRecord(eFork, 0);
    cudaStreamWaitEvent(s2, eFork, 0);
    cudaStreamWaitEvent(s3, eFork, 0);

    k_wt<<<dim3(D_FEAT / 32, NTOT / 32), dim3(32, 8), 0, s2>>>(Wa, Ws, Wc);
    cudaEventRecord(eWt, s2);
    k_zero<<<1, 64, 0, s2>>>();
    k_hist<<<N_REL / 1024, 1024, 0, s2>>>(lab);
    k_scan<<<1, 32, 0, s2>>>();
    k_rank<<<N_CLS, 1024, 0, s2>>>(lab);
    k_pairs<<<N_REL / 256, 256, 0, s2>>>(lab);
    cudaEventRecord(eJoin, s2);

    for (int c = 0; c < NCHUNK; c++) {
        k_xh<<<1024, 256, 0, s3>>>(X, c * ROWS_PER_CHUNK);
        cudaEventRecord(eX[c], s3);
    }

    for (int c = 0; c < NCHUNK; c++) {
        if (c == 0) cudaStreamWaitEvent(0, eWt, 0);   // GEMM needs converted weights
        cudaStreamWaitEvent(0, eX[c], 0);
        dim3 grid(NTOT / TN, MT_PER_CHUNK);   // (6, 32)
        k_gemm<<<grid, 256, SMEM_TOTAL>>>(tmA, tmB, X, Wa, Ws, Wc,
                                          (__half*)y_ptr, c * MT_PER_CHUNK);
        cudaEventRecord(eG[c], 0);
    }

    // overlapped k_out parts on s2 (writes are row-disjoint across parts):
    //  part1: rows with max-chunk <= 5  — needs GEMM chunks 0..5 (eG[5], main is serial)
    cudaStreamWaitEvent(s2, eG[5], 0);     // index chain already done on s2
    k_out<<<M, 192, 0, s2>>>(ba, bs, bc, out, M, 0, 6);
    //  part2: rows with max-chunk == 6 — needs chunks 0..6
    cudaStreamWaitEvent(s2, eG[6], 0);
    k_out<<<M, 192, 0, s2>>>(ba, bs, bc, out, M, 6, 7);
    cudaEventRecord(eP2, s2);

    //  part3 (final): rows touching chunk 7 — on main after the last GEMM chunk
    cudaStreamWaitEvent(0, eJoin, 0);      // index chain (for safety/ordering)
    k_out<<<M, 192>>>(ba, bs, bc, out, M, 7, 8);
    cudaStreamWaitEvent(0, eP2, 0);        // join s2 leaf work back into main
}

// round 15
// speedup vs baseline: 1.1732x; 1.1732x over previous
#include <cuda_runtime.h>
#include <cuda.h>
#include <cuda_fp16.h>
#include <cstdint>

#define N_REL   65536
#define D_FEAT  3872
#define D_OUT   512
#define N_CLS   36
#define NTOT    1536            // 3 heads * 512
#define KCHUNK  64              // halfs per K tile (128 bytes)
#define NK      61              // ceil(3872/64); last chunk TMA zero-fills 32 halfs
#define TM      256             // per-CTA M (2 x 128-row MMAs)
#define TN      256
#define STAGES  3
#define STAGE_BYTES 65536       // A 32KB + B 32KB
#define NCHUNK  4               // X-convert / GEMM pipeline chunks
#define MT_PER_CHUNK (N_REL / TM / NCHUNK)   // 64 M-tiles per chunk
#define ROWS_PER_CHUNK (N_REL / NCHUNK)      // 16384 rows

#if defined(__CUDA_ARCH_FEAT_SM103_ALL) || defined(__CUDA_ARCH_FEAT_SM100_ALL) || defined(__CUDA_ARCH_FEAT_SM101_ALL)
#define HAS_TCGEN05 1
#else
#define HAS_TCGEN05 0
#endif

// ---------------- device scratch ----------------
__device__ int g_cnt[N_CLS];
__device__ int g_off[N_CLS + 1];
__device__ int g_poff[N_CLS];
__device__ int g_sorted[N_REL];
__device__ int g_lo[N_REL];
__device__ int g_hi[N_REL];
__device__ __half g_wth[(size_t)NTOT * D_FEAT];        // 12 MB, K-major fp16 weights
__device__ __half g_xh[(size_t)N_REL * D_FEAT];        // 483 MB, fp16 X
__device__ __half g_yh[(size_t)N_REL * NTOT];          // 201 MB, Y = X @ W (fp16, no bias)

// ---------------- PTX helpers ----------------
__device__ __forceinline__ uint32_t smem_to_u32(const void* p) {
    uint32_t a;
    asm("{ .reg .u64 t; cvta.to.shared.u64 t, %1; cvt.u32.u64 %0, t; }" : "=r"(a) : "l"(p));
    return a;
}
#define MBARRIER_INIT(mbar, cnt) \
    asm volatile("mbarrier.init.shared.b64 [%0], %1;" :: "r"((uint32_t)(mbar)), "r"((uint32_t)(cnt)) : "memory")
#define MBARRIER_EXPECT_TX(mbar, bytes) \
    asm volatile("mbarrier.arrive.expect_tx.shared.b64 _, [%0], %1;" \
                 :: "r"((uint32_t)(mbar)), "r"((uint32_t)(bytes)) : "memory")
#define MBARRIER_WAIT_PARITY(mbar, par) do {                                        \
    uint32_t _m = (uint32_t)(mbar); uint32_t _p = (uint32_t)(par); uint32_t _d;     \
    asm volatile("{\n\t.reg .pred p;\n\t"                                           \
        "mbarrier.try_wait.parity.acquire.cta.shared::cta.b64 p, [%1], %2;\n\t"     \
        "selp.b32 %0, 1, 0, p;\n\t}" : "=r"(_d) : "r"(_m), "r"(_p) : "memory");     \
    if (!_d) {                                                                      \
        asm volatile("{\n\t.reg .pred P1;\n\t"                                      \
        "WL_%=:\n\tmbarrier.try_wait.parity.acquire.cta.shared::cta.b64 P1, [%0], %1, 0x989680;\n\t" \
        "@P1 bra.uni WD_%=;\n\tbra.uni WL_%=;\n\tWD_%=:\n\t}"                       \
        :: "r"(_m), "r"(_p) : "memory");                                            \
    } } while (0)

#if HAS_TCGEN05
__device__ __forceinline__ uint32_t elect_one_pred() {
    uint32_t pred;
    asm volatile("{\n\t.reg .pred p;\n\telect.sync _|p, 0xFFFFFFFF;\n\tselp.b32 %0, 1, 0, p;\n\t}"
                 : "=r"(pred));
    return pred;
}
#define TMA_LOAD_2D(smem, tmap, cx, cy, mbar) \
    asm volatile("cp.async.bulk.tensor.2d.shared::cta.global.tile.mbarrier::complete_tx::bytes " \
                 "[%0], [%1, {%2, %3}], [%4];" \
                 :: "r"((uint32_t)(smem)), "l"(tmap), "r"((int)(cx)), "r"((int)(cy)), \
                    "r"((uint32_t)(mbar)) : "memory")
#define TCGEN05_ALLOC(sr, nc) \
    asm volatile("tcgen05.alloc.cta_group::1.sync.aligned.shared::cta.b32 [%0], %1;" \
                 :: "r"((uint32_t)(sr)), "r"((uint32_t)(nc)) : "memory")
#define TCGEN05_DEALLOC(t, nc) \
    asm volatile("tcgen05.dealloc.cta_group::1.sync.aligned.b32 %0, %1;" :: "r"(t), "r"((uint32_t)(nc)))
#define TCGEN05_RELINQ() \
    asm volatile("tcgen05.relinquish_alloc_permit.cta_group::1.sync.aligned;")
#define TCGEN05_COMMIT(mbar) \
    asm volatile("tcgen05.commit.cta_group::1.mbarrier::arrive::one.shared::cluster.b64 [%0];" \
                 :: "r"((uint32_t)(mbar)) : "memory")
#define TCGEN05_FENCE_AFTER()  asm volatile("tcgen05.fence::after_thread_sync;" ::: "memory")
#define TCGEN05_FENCE_BEFORE() asm volatile("tcgen05.fence::before_thread_sync;" ::: "memory")
#define TCGEN05_WAIT_LD()      asm volatile("tcgen05.wait::ld.sync.aligned;" ::: "memory")
#define TCGEN05_LD_X32(r, ta) \
    asm volatile("tcgen05.ld.sync.aligned.32x32b.x32.b32 " \
        "{%0,%1,%2,%3,%4,%5,%6,%7,%8,%9,%10,%11,%12,%13,%14,%15," \
        "%16,%17,%18,%19,%20,%21,%22,%23,%24,%25,%26,%27,%28,%29,%30,%31}, [%32];" \
        : "=r"((r)[0]),"=r"((r)[1]),"=r"((r)[2]),"=r"((r)[3]),"=r"((r)[4]),"=r"((r)[5]),"=r"((r)[6]),"=r"((r)[7]), \
          "=r"((r)[8]),"=r"((r)[9]),"=r"((r)[10]),"=r"((r)[11]),"=r"((r)[12]),"=r"((r)[13]),"=r"((r)[14]),"=r"((r)[15]), \
          "=r"((r)[16]),"=r"((r)[17]),"=r"((r)[18]),"=r"((r)[19]),"=r"((r)[20]),"=r"((r)[21]),"=r"((r)[22]),"=r"((r)[23]), \
          "=r"((r)[24]),"=r"((r)[25]),"=r"((r)[26]),"=r"((r)[27]),"=r"((r)[28]),"=r"((r)[29]),"=r"((r)[30]),"=r"((r)[31]) \
        : "r"(ta))

static constexpr uint64_t SMEM_DESC_BASE_SW128 =
    (uint64_t(2) << 61) | (uint64_t(1) << 46) | (uint64_t(64) << 32) | (uint64_t(1) << 16);
__device__ __forceinline__ uint64_t make_desc(uint32_t addr) {
    return SMEM_DESC_BASE_SW128 | ((uint64_t)(addr >> 4) & 0x3FFF);
}
// kind::f16 SS MMA (fp16 in, fp32 accum)
__device__ __forceinline__ void mma_f16_ss(uint32_t d, uint64_t a, uint64_t b,
                                           uint32_t idesc, uint32_t en) {
    asm volatile("{\n\t.reg .pred p;\n\tsetp.ne.u32 p, %5, 0;\n\t"
        "tcgen05.mma.cta_group::1.kind::f16 [%0], %1, %2, %3, {%4, %4, %4, %4}, p;\n\t}"
        :: "r"(d), "l"(a), "l"(b), "r"(idesc), "r"(0u), "r"(en) : "memory");
}
// dtype=f32(1)<<4 | atype=F16(0)<<7 | btype=F16(0)<<10 | N=256 | M=128
static constexpr uint32_t IDESC = (1u << 4) | ((TN / 8) << 17) | ((128 / 16) << 24);
#endif  // HAS_TCGEN05

// ---------------- index construction ----------------
__global__ void k_zero() { if (threadIdx.x < N_CLS) g_cnt[threadIdx.x] = 0; }

__global__ void k_hist(const int* __restrict__ lab) {     // <<<64, 1024>>>
    __shared__ int h[N_CLS];
    if (threadIdx.x < N_CLS) h[threadIdx.x] = 0;
    __syncthreads();
    int i = blockIdx.x * blockDim.x + threadIdx.x;
    atomicAdd(&h[lab[i]], 1);
    __syncthreads();
    if (threadIdx.x < N_CLS) atomicAdd(&g_cnt[threadIdx.x], h[threadIdx.x]);
}
__global__ void k_scan() {
    if (threadIdx.x == 0) {
        int run = 0, prun = 0;
        g_off[0] = 0;
        for (int c = 0; c < N_CLS; c++) {
            g_poff[c] = prun;
            int cnt = g_cnt[c];
            run += cnt; g_off[c + 1] = run;
            prun += (cnt > 0) ? (cnt - 1) : 0;
        }
    }
}
__global__ void k_rank(const int* __restrict__ lab) {     // <<<36, 1024>>>
    const int c = blockIdx.x, tid = threadIdx.x;
    __shared__ int wsum[32];
    const int base_off = g_off[c];
    int sbase = 0;
    for (int start = 0; start < N_REL; start += 1024) {
        int i = start + tid;
        int flag = (lab[i] == c) ? 1 : 0;
        unsigned mask = __ballot_sync(0xffffffffu, flag);
        if ((tid & 31) == 0) wsum[tid >> 5] = __popc(mask);
        __syncthreads();
        int wbase = 0, total = 0, wi = tid >> 5;
        #pragma unroll
        for (int j = 0; j < 32; j++) { int v = wsum[j]; total += v; if (j < wi) wbase += v; }
        if (flag) {
            int excl = __popc(mask & ((1u << (tid & 31)) - 1u));
            g_sorted[base_off + sbase + wbase + excl] = i;
        }
        sbase += total;
        __syncthreads();
    }
}
__global__ void k_pairs(const int* __restrict__ lab) {
    int p = blockIdx.x * blockDim.x + threadIdx.x;
    if (p >= N_REL) return;
    int io = g_sorted[p];
    int c = lab[io];
    if (p + 1 < g_off[c + 1]) {
        int m = p - g_off[c] + g_poff[c];
        g_lo[m] = io; g_hi[m] = g_sorted[p + 1];
    }
}

// ---------------- convert an X row-chunk to fp16 ----------------
__global__ void k_xh(const float* __restrict__ X, int row0) {   // <<<2048, 256>>>
    const size_t base = (size_t)row0 * D_FEAT / 4;
    const size_t total = (size_t)ROWS_PER_CHUNK * D_FEAT / 4;
    const float4* __restrict__ src = (const float4*)X + base;
    __half2* __restrict__ dst = (__half2*)g_xh + base * 2;
    for (size_t q = (size_t)blockIdx.x * blockDim.x + threadIdx.x;
         q < total; q += (size_t)gridDim.x * blockDim.x) {
        float4 v = src[q];
        dst[q * 2]     = __floats2half2_rn(v.x, v.y);
        dst[q * 2 + 1] = __floats2half2_rn(v.z, v.w);
    }
}

// ---------------- transpose + convert weights to K-major fp16 ----------------
__global__ void k_wt(const float* __restrict__ Wa, const float* __restrict__ Ws,
                     const float* __restrict__ Wc) {
    __shared__ float tile[32][33];
    int kb = blockIdx.x * 32;
    int ng = blockIdx.y;
    int head = ng >> 4;
    const float* W = (head == 0) ? Wa : ((head == 1) ? Ws : Wc);
    int nb = (ng & 15) * 32;
    int tx = threadIdx.x, ty = threadIdx.y;  // (32, 8)
    #pragma unroll
    for (int r = 0; r < 4; r++) {
        int k = kb + ty + r * 8;
        tile[ty + r * 8][tx] = W[(size_t)k * D_OUT + nb + tx];
    }
    __syncthreads();
    #pragma unroll
    for (int r = 0; r < 4; r++) {
        int n = ng * 32 + ty + r * 8;
        g_wth[(size_t)n * D_FEAT + kb + tx] = __float2half_rn(tile[tx][ty + r * 8]);
    }
}

// ---------------- output diff epilogue: out = Y[hi] - Y[lo] + bias ----------------
__global__ void k_out(const float* __restrict__ ba, const float* __restrict__ bs,
                      const float* __restrict__ bc, float* __restrict__ out, int M) {
    const int m = blockIdx.x;
    const int q = threadIdx.x;                 // 0..191, one uint4 (8 halfs) each
    const uint4* __restrict__ yh = (const uint4*)(g_yh + (size_t)g_hi[m] * NTOT);
    const uint4* __restrict__ yl = (const uint4*)(g_yh + (size_t)g_lo[m] * NTOT);
    uint4 A = yh[q], B = yl[q];
    const int col = q * 8;
    const int h = col >> 9;                    // head
    const int c = col & 511;                   // col within head
    const float* bias = (h == 0) ? ba : ((h == 1) ? bs : bc);
    float4 b0 = *(const float4*)(bias + c);
    float4 b1 = *(const float4*)(bias + c + 4);
    float2 a0 = __half22float2(*(__half2*)&A.x), l0 = __half22float2(*(__half2*)&B.x);
    float2 a1 = __half22float2(*(__half2*)&A.y), l1 = __half22float2(*(__half2*)&B.y);
    float2 a2 = __half22float2(*(__half2*)&A.z), l2 = __half22float2(*(__half2*)&B.z);
    float2 a3 = __half22float2(*(__half2*)&A.w), l3 = __half22float2(*(__half2*)&B.w);
    float* dst = out + ((size_t)h * M + m) * D_OUT + c;
    float4 o0, o1;
    o0.x = a0.x - l0.x + b0.x; o0.y = a0.y - l0.y + b0.y;
    o0.z = a1.x - l1.x + b0.z; o0.w = a1.y - l1.y + b0.w;
    o1.x = a2.x - l2.x + b1.x; o1.y = a2.y - l2.y + b1.y;
    o1.z = a3.x - l3.x + b1.z; o1.w = a3.y - l3.y + b1.w;
    *(float4*)(dst)     = o0;
    *(float4*)(dst + 4) = o1;
}

// ---------------- GEMM: Y = Xh @ Wth^T (fp16 in, fp32 accum, fp16 out) --------
// grid: x = 6 N-tiles (256 cols), y = 64 M-tiles per chunk; 256 threads.
__global__ __launch_bounds__(256, 1)
void k_gemm(const __grid_constant__ CUtensorMap tmA,
            const __grid_constant__ CUtensorMap tmB,
            const float* __restrict__ X,
            const float* __restrict__ Wa, const float* __restrict__ Ws,
            const float* __restrict__ Wc, __half* __restrict__ y, int yoff) {
    extern __shared__ char smem[];
#if HAS_TCGEN05
    // ======================= tcgen05 f16 + TMA path =======================
    const uint32_t sb = smem_to_u32(smem);
    // layout: [0..4) tmem ptr | [8..32) full[3] | [32..56) empty[3] | data @1024
    const uint32_t full0  = sb + 8;
    const uint32_t empty0 = sb + 32;
    const uint32_t data = (sb + 56 + 1023) & ~1023u;

    const int tid = threadIdx.x;
    const int wid = tid >> 5;
    const int lid = tid & 31;
    const int m0 = (blockIdx.y + yoff) * TM;
    const int n0 = blockIdx.x * TN;

    if (wid == 0) TCGEN05_ALLOC(sb, 512);
    if (tid == 0) {
        #pragma unroll
        for (int s = 0; s < STAGES; s++) {
            MBARRIER_INIT(full0 + s * 8, 1);     // expect_tx thread arrives
            MBARRIER_INIT(empty0 + s * 8, 1);    // tcgen05 commit arrives
        }
    }
    __syncthreads();
    uint32_t tmem;
    asm volatile("ld.shared.b32 %0, [%1];" : "=r"(tmem) : "r"(sb));

    const bool leader = (wid == 0) && elect_one_pred();

    if (leader) {
        // prologue: fill all stages
        #pragma unroll
        for (int i = 0; i < STAGES; i++) {
            uint32_t A_base = data + (uint32_t)i * STAGE_BYTES;
            MBARRIER_EXPECT_TX(full0 + i * 8, 2 * 32768u);
            TMA_LOAD_2D(A_base,          &tmA, i * KCHUNK, m0, full0 + i * 8);
            TMA_LOAD_2D(A_base + 32768u, &tmB, i * KCHUNK, n0, full0 + i * 8);
        }
        int s = 0, ph = 0;   // ph = (i / STAGES) & 1
        for (int i = 0; i < NK; i++) {
            const uint32_t A_base = data + (uint32_t)s * STAGE_BYTES;
            const uint32_t B_base = A_base + 32768u;
            MBARRIER_WAIT_PARITY(full0 + s * 8, ph);    // tiles arrived
            uint64_t ad0 = make_desc(A_base);
            uint64_t ad1 = make_desc(A_base + 16384u);   // rows 128..255
            uint64_t bd  = make_desc(B_base);
            #pragma unroll
            for (int ks = 0; ks < 4; ks++) {             // 4 x K=16 halfs = 64
                uint32_t en = (i > 0 || ks > 0) ? 1u : 0u;
                mma_f16_ss(tmem,       ad0 + ks * 2, bd + ks * 2, IDESC, en);
                mma_f16_ss(tmem + 256, ad1 + ks * 2, bd + ks * 2, IDESC, en);
            }
            TCGEN05_COMMIT(empty0 + s * 8);
            const int j = i + STAGES;
            if (j < NK) {
                // reuse stage s: wait for chunk i's MMAs to finish reading it
                MBARRIER_WAIT_PARITY(empty0 + s * 8, ph);
                MBARRIER_EXPECT_TX(full0 + s * 8, 2 * 32768u);
                TMA_LOAD_2D(A_base, &tmA, j * KCHUNK, m0, full0 + s * 8);
                TMA_LOAD_2D(B_base, &tmB, j * KCHUNK, n0, full0 + s * 8);
            }
            if (++s == STAGES) { s = 0; ph ^= 1; }
        }
        // leader is phase-paced: this waits for the FINAL commit (chunk NK-1)
        MBARRIER_WAIT_PARITY(empty0 + ((NK - 1) % STAGES) * 8, ((NK - 1) / STAGES) & 1);
    }
    __syncthreads();          // release all warps only after leader saw final commit
    TCGEN05_FENCE_AFTER();

    // epilogue: warps 0-3 -> rows m0..m0+127 (TMEM cols 0..255),
    //           warps 4-7 -> rows m0+128..m0+255 (TMEM cols 256..511)
    const uint32_t dbase = tmem + ((wid >= 4) ? 256u : 0u);
    const int m = m0 + ((wid >= 4) ? 128 : 0) + (wid & 3) * 32 + lid;
    __half* dst_row = y + (size_t)m * NTOT + n0;

    #pragma unroll
    for (int cc = 0; cc < 256; cc += 32) {
        uint32_t r[32];
        TCGEN05_LD_X32(r, dbase + cc);
        TCGEN05_WAIT_LD();
        #pragma unroll
        for (int q = 0; q < 4; q++) {
            __half2 h0 = __floats2half2_rn(__uint_as_float(r[q*8+0]), __uint_as_float(r[q*8+1]));
            __half2 h1 = __floats2half2_rn(__uint_as_float(r[q*8+2]), __uint_as_float(r[q*8+3]));
            __half2 h2 = __floats2half2_rn(__uint_as_float(r[q*8+4]), __uint_as_float(r[q*8+5]));
            __half2 h3 = __floats2half2_rn(__uint_as_float(r[q*8+6]), __uint_as_float(r[q*8+7]));
            uint4 o;
            o.x = *(uint32_t*)&h0; o.y = *(uint32_t*)&h1;
            o.z = *(uint32_t*)&h2; o.w = *(uint32_t*)&h3;
            *(uint4*)(dst_row + cc + q * 8) = o;
        }
    }
    TCGEN05_FENCE_BEFORE();
    __syncthreads();
    if (wid == 0) {
        TCGEN05_RELINQ();
        TCGEN05_DEALLOC(tmem, 512);
    }
#else
    // ======================= SIMT fallback (compute_103 pass) =======================
    float (*As)[128] = (float(*)[128])smem;                       // [16][128]
    float (*Bs)[128] = (float(*)[128])(smem + 16 * 128 * 4);      // [16][128]
    const int tid = threadIdx.x;
    const int tx = tid & 15;
    const int ty = tid >> 4;

    for (int mh = 0; mh < 2; mh++) {
        const int m0 = (blockIdx.y + yoff) * TM + mh * 128;
        for (int h = 0; h < 2; h++) {
            const int n0 = blockIdx.x * TN + h * 128;
            const int head = n0 / D_OUT;
            const int ncl = n0 % D_OUT;
            const float* __restrict__ W = (head == 0) ? Wa : ((head == 1) ? Ws : Wc);

            float acc[8][8];
            #pragma unroll
            for (int i = 0; i < 8; i++)
                #pragma unroll
                for (int j = 0; j < 8; j++) acc[i][j] = 0.0f;

            for (int k0 = 0; k0 < D_FEAT; k0 += 16) {
                #pragma unroll
                for (int jj = 0; jj < 2; jj++) {
                    int idx = tid * 2 + jj;
                    int row = idx >> 2, kq = idx & 3;
                    float4 v = *(const float4*)(X + (size_t)(m0 + row) * D_FEAT + k0 + kq * 4);
                    As[kq * 4 + 0][row] = v.x; As[kq * 4 + 1][row] = v.y;
                    As[kq * 4 + 2][row] = v.z; As[kq * 4 + 3][row] = v.w;
                }
                #pragma unroll
                for (int jj = 0; jj < 2; jj++) {
                    int l = tid * 2 + jj;
                    int k = l >> 5, nq = l & 31;
                    *(float4*)&Bs[k][nq * 4] =
                        *(const float4*)(W + (size_t)(k0 + k) * D_OUT + ncl + nq * 4);
                }
                __syncthreads();
                #pragma unroll
                for (int k = 0; k < 16; k++) {
                    float4 a0 = *(const float4*)&As[k][ty * 8];
                    float4 a1 = *(const float4*)&As[k][ty * 8 + 4];
                    float4 b0 = *(const float4*)&Bs[k][tx * 8];
                    float4 b1 = *(const float4*)&Bs[k][tx * 8 + 4];
                    float av[8] = {a0.x, a0.y, a0.z, a0.w, a1.x, a1.y, a1.z, a1.w};
                    float bv[8] = {b0.x, b0.y, b0.z, b0.w, b1.x, b1.y, b1.z, b1.w};
                    #pragma unroll
                    for (int i = 0; i < 8; i++)
                        #pragma unroll
                        for (int j = 0; j < 8; j++)
                            acc[i][j] = fmaf(av[i], bv[j], acc[i][j]);
                }
                __syncthreads();
            }

            #pragma unroll
            for (int i = 0; i < 8; i++) {
                int gm = (blockIdx.y + yoff) * TM + mh * 128 + ty * 8 + i;
                __half* dst = y + (size_t)gm * NTOT + n0 + tx * 8;
                #pragma unroll
                for (int j = 0; j < 8; j++) dst[j] = __float2half_rn(acc[i][j]);
            }
            __syncthreads();
        }
    }
#endif
}

// ---------------- launch ----------------
typedef CUresult (*encode_fn_t)(CUtensorMap*, CUtensorMapDataType, cuuint32_t, void*,
                                const cuuint64_t*, const cuuint64_t*, const cuuint32_t*,
                                const cuuint32_t*, CUtensorMapInterleave, CUtensorMapSwizzle,
                                CUtensorMapL2promotion, CUtensorMapFloatOOBfill);

static void make_tmap_f16(encode_fn_t enc, CUtensorMap* tm, void* base,
                          unsigned long long rows) {
    cuuint64_t dims[2]    = { (cuuint64_t)D_FEAT, (cuuint64_t)rows };
    cuuint64_t strides[1] = { (cuuint64_t)D_FEAT * sizeof(__half) };
    cuuint32_t box[2]     = { KCHUNK, 256u };    // 64 halfs = 128B (SW128 limit)
    cuuint32_t estr[2]    = { 1u, 1u };
    enc(tm, CU_TENSOR_MAP_DATA_TYPE_FLOAT16, 2, base, dims, strides, box, estr,
        CU_TENSOR_MAP_INTERLEAVE_NONE, CU_TENSOR_MAP_SWIZZLE_128B,
        CU_TENSOR_MAP_L2_PROMOTION_L2_128B, CU_TENSOR_MAP_FLOAT_OOB_FILL_NONE);
}

extern "C" void kernel_launch(void* const* d_in, const int* in_sizes, int n_in,
                              void* d_out, int out_size) {
    const float* X   = (const float*)d_in[0];
    const float* Wa  = (const float*)d_in[1];
    const float* ba  = (const float*)d_in[2];
    const float* Ws  = (const float*)d_in[3];
    const float* bs  = (const float*)d_in[4];
    const float* Wc  = (const float*)d_in[5];
    const float* bc  = (const float*)d_in[6];
    const int*   lab = (const int*)d_in[7];
    float* out = (float*)d_out;

    const int M = out_size / (3 * D_OUT);
    const int SMEM_TOTAL = STAGE_BYTES * STAGES + 1024 + 128;   // ~197.8 KB

    cudaFuncSetAttribute(k_gemm, cudaFuncAttributeMaxDynamicSharedMemorySize, SMEM_TOTAL);

    // one-time host objects (no device allocations) — proven R10 configuration.
    static encode_fn_t enc = nullptr;
    static cudaStream_t s2 = nullptr, s3 = nullptr;
    static cudaEvent_t eFork = nullptr, eJoin = nullptr, eWt = nullptr;
    static cudaEvent_t eX[NCHUNK] = {};
    if (!enc) {
        cudaDriverEntryPointQueryResult qr;
        void* fp = nullptr;
#if CUDART_VERSION >= 12050
        cudaGetDriverEntryPointByVersion("cuTensorMapEncodeTiled", &fp, 12000,
                                         cudaEnableDefault, &qr);
#else
        cudaGetDriverEntryPoint("cuTensorMapEncodeTiled", &fp, cudaEnableDefault, &qr);
#endif
        enc = (encode_fn_t)fp;
    }
    if (!s2) {
        cudaStreamCreateWithFlags(&s2, cudaStreamNonBlocking);
        cudaStreamCreateWithFlags(&s3, cudaStreamNonBlocking);
        cudaEventCreateWithFlags(&eFork, cudaEventDisableTiming);
        cudaEventCreateWithFlags(&eJoin, cudaEventDisableTiming);
        cudaEventCreateWithFlags(&eWt, cudaEventDisableTiming);
        for (int c = 0; c < NCHUNK; c++)
            cudaEventCreateWithFlags(&eX[c], cudaEventDisableTiming);
    }

    void* wth_ptr = nullptr;
    cudaGetSymbolAddress(&wth_ptr, g_wth);
    void* xh_ptr = nullptr;
    cudaGetSymbolAddress(&xh_ptr, g_xh);
    void* y_ptr = nullptr;
    cudaGetSymbolAddress(&y_ptr, g_yh);

    CUtensorMap tmA, tmB;
    make_tmap_f16(enc, &tmA, xh_ptr, N_REL);
    make_tmap_f16(enc, &tmB, wth_ptr, NTOT);

    // fork: s2 = weights + index chain; s3 = X conversion chunks; main = GEMM
    cudaEventRecord(eFork, 0);
    cudaStreamWaitEvent(s2, eFork, 0);
    cudaStreamWaitEvent(s3, eFork, 0);

    k_wt<<<dim3(D_FEAT / 32, NTOT / 32), dim3(32, 8), 0, s2>>>(Wa, Ws, Wc);
    cudaEventRecord(eWt, s2);
    k_zero<<<1, 64, 0, s2>>>();
    k_hist<<<N_REL / 1024, 1024, 0, s2>>>(lab);
    k_scan<<<1, 32, 0, s2>>>();
    k_rank<<<N_CLS, 1024, 0, s2>>>(lab);
    k_pairs<<<N_REL / 256, 256, 0, s2>>>(lab);
    cudaEventRecord(eJoin, s2);

    for (int c = 0; c < NCHUNK; c++) {
        k_xh<<<2048, 256, 0, s3>>>(X, c * ROWS_PER_CHUNK);
        cudaEventRecord(eX[c], s3);
    }

    cudaStreamWaitEvent(0, eWt, 0);      // GEMM needs converted weights
    for (int c = 0; c < NCHUNK; c++) {
        cudaStreamWaitEvent(0, eX[c], 0);
        dim3 grid(NTOT / TN, MT_PER_CHUNK);   // (6, 64)
        k_gemm<<<grid, 256, SMEM_TOTAL>>>(tmA, tmB, X, Wa, Ws, Wc,
                                          (__half*)y_ptr, c * MT_PER_CHUNK);
    }

    // join: k_out needs the GEMM (main stream) and the index chain (s2)
    cudaStreamWaitEvent(0, eJoin, 0);
    k_out<<<M, 192>>>(ba, bs, bc, out, M);
}